// round 2
// baseline (speedup 1.0000x reference)
#include <cuda_runtime.h>
#include <cuda_bf16.h>
#include <cstdint>

#define D        256
#define K        1024
#define NROWS    65536
#define ROWS_BLK 128
#define COLS_TILE 128
#define NTILES   (K / COLS_TILE)   // 8
#define NT8      16                 // n-tiles of 8 within a 128-col tile
#define KSTEPS   16                 // 256 / 16
#define PADB     544                // smem row stride in bytes (272 bf16) -> 8-bank shift/row
#define DELTA    3.0f
#define ND       (NROWS * D)        // 16777216

// ---- device scratch (no allocations allowed) ----
__device__ __nv_bfloat16 g_cbp[K * D];   // bf16 codebook, k-permuted
__device__ float  g_cn[K];               // fp32 row norms ||c||^2 (screen)
__device__ double g_cnd[K];              // fp64 row norms ||c||^2 (rescore)
__device__ int    g_counts[K];
__device__ int    g_idx[NROWS];

// permutation within each 16-element k chunk so a quad-lane LDS.64 yields
// {k=2q,2q+1, k=2q+8,2q+9} = exactly one mma fragment register pair.
__device__ __host__ __forceinline__ int permpos(int d) {
    int chunk = d >> 4, m = d & 15;
    return (chunk << 4) + (((m & 7) >> 1) << 2) + ((m >> 3) << 1) + (m & 1);
}

// ------------------- kernel 0: prep -------------------
__global__ void vq_prep(const float* __restrict__ cb) {
    int t = blockIdx.x * blockDim.x + threadIdx.x;
    if (t >= K) return;
    const float* row = cb + (size_t)t * D;
    float  nrm  = 0.f;
    double nrmd = 0.0;
    for (int d = 0; d < D; d++) {
        float v = row[d];
        nrm  += v * v;
        nrmd += (double)v * (double)v;
        g_cbp[t * D + permpos(d)] = __float2bfloat16(v);
    }
    g_cn[t]  = nrm;
    g_cnd[t] = nrmd;
    g_counts[t] = 0;
}

// top-4 insertion (strict <, so earlier (smaller) indices win ties)
__device__ __forceinline__ void ins4(float (&v)[4], int (&ix)[4], float x, int c) {
    if (x < v[3]) {
        if (x < v[1]) {
            if (x < v[0]) {
                v[3]=v[2]; ix[3]=ix[2]; v[2]=v[1]; ix[2]=ix[1];
                v[1]=v[0]; ix[1]=ix[0]; v[0]=x; ix[0]=c;
            } else {
                v[3]=v[2]; ix[3]=ix[2]; v[2]=v[1]; ix[2]=ix[1];
                v[1]=x; ix[1]=c;
            }
        } else {
            if (x < v[2]) { v[3]=v[2]; ix[3]=ix[2]; v[2]=x; ix[2]=c; }
            else          { v[3]=x; ix[3]=c; }
        }
    }
}

// ------------------- kernel 1: main screen + rescore -------------------
#define SMEM_Z    0
#define SMEM_CB0  (ROWS_BLK * PADB)                 // 69632
#define SMEM_CB1  (SMEM_CB0 + COLS_TILE * PADB)     // 139264
#define SMEM_TOT  (SMEM_CB1 + COLS_TILE * PADB)     // 208896

__global__ __launch_bounds__(256, 1)
void vq_main(const float* __restrict__ z, const float* __restrict__ cb) {
    extern __shared__ char sm[];
    const int tid  = threadIdx.x;
    const int wid  = tid >> 5;
    const int lane = tid & 31;
    const int gid  = lane >> 2;
    const int t4   = lane & 3;
    const int row0 = blockIdx.x * ROWS_BLK;

    // cp.async copy of a 128-col codebook tile (already bf16+permuted in gmem)
    auto copy_tile = [&](int ct, int buf) {
        const char* src = (const char*)g_cbp + (size_t)ct * COLS_TILE * D * 2;
        char* dstb = sm + (buf ? SMEM_CB1 : SMEM_CB0);
        #pragma unroll
        for (int i = 0; i < 16; i++) {
            int idx = i * 256 + tid;           // 4096 chunks of 16B
            int r = idx >> 5, c = idx & 31;
            uint32_t da = (uint32_t)__cvta_generic_to_shared(dstb + r * PADB + c * 16);
            const char* s = src + r * (D * 2) + c * 16;
            asm volatile("cp.async.cg.shared.global [%0], [%1], 16;\n" :: "r"(da), "l"(s));
        }
        asm volatile("cp.async.commit_group;\n");
    };

    copy_tile(0, 0);

    // stage z tile: fp32 -> bf16, permuted layout
    {
        const float* zsrc = z + (size_t)row0 * D;
        #pragma unroll 4
        for (int i = 0; i < 64; i++) {
            int idx = i * 256 + tid;           // 16384 bf16 pairs
            int r = idx >> 7, j = idx & 127;
            int k = 2 * j;
            float2 v = *(const float2*)(zsrc + (size_t)r * D + k);
            __nv_bfloat162 b = __floats2bfloat162_rn(v.x, v.y);
            *(uint32_t*)(sm + SMEM_Z + r * PADB + permpos(k) * 2) = *(uint32_t*)&b;
        }
    }

    // per-lane top-4 for 2 row slots (rows gid and gid+8 of this warp's m-tile)
    float tv[2][4]; int ti[2][4];
    #pragma unroll
    for (int s = 0; s < 2; s++)
        #pragma unroll
        for (int j = 0; j < 4; j++) { tv[s][j] = 3.4e38f; ti[s][j] = 0; }

    const int rb = wid * 16;
    const uint32_t a_base = (uint32_t)(SMEM_Z + (rb + gid) * PADB + t4 * 8);

    for (int tile = 0; tile < NTILES; tile++) {
        asm volatile("cp.async.wait_group 0;\n" ::: "memory");
        __syncthreads();
        if (tile + 1 < NTILES) copy_tile(tile + 1, (tile + 1) & 1);

        float acc[NT8][4];
        #pragma unroll
        for (int nt = 0; nt < NT8; nt++)
            acc[nt][0] = acc[nt][1] = acc[nt][2] = acc[nt][3] = 0.f;

        const char* cbbuf = sm + ((tile & 1) ? SMEM_CB1 : SMEM_CB0);

        #pragma unroll 4
        for (int ks = 0; ks < KSTEPS; ks++) {
            uint2 alo = *(const uint2*)(sm + a_base + ks * 32);
            uint2 ahi = *(const uint2*)(sm + a_base + 8 * PADB + ks * 32);
            uint32_t a0 = alo.x, a2 = alo.y, a1 = ahi.x, a3 = ahi.y;
            #pragma unroll
            for (int nt = 0; nt < NT8; nt++) {
                uint2 bb = *(const uint2*)(cbbuf + (nt * 8 + gid) * PADB + t4 * 8 + ks * 32);
                asm volatile(
                    "mma.sync.aligned.m16n8k16.row.col.f32.bf16.bf16.f32 "
                    "{%0,%1,%2,%3}, {%4,%5,%6,%7}, {%8,%9}, {%0,%1,%2,%3};\n"
                    : "+f"(acc[nt][0]), "+f"(acc[nt][1]), "+f"(acc[nt][2]), "+f"(acc[nt][3])
                    : "r"(a0), "r"(a1), "r"(a2), "r"(a3), "r"(bb.x), "r"(bb.y));
            }
        }

        // epilogue: cost = ||c||^2 - 2*score, push into top-4
        int colbase = tile * COLS_TILE + 2 * t4;
        #pragma unroll
        for (int nt = 0; nt < NT8; nt++) {
            int c0 = colbase + nt * 8;
            float cn0 = __ldg(&g_cn[c0]);
            float cn1 = __ldg(&g_cn[c0 + 1]);
            ins4(tv[0], ti[0], cn0 - 2.f * acc[nt][0], c0);
            ins4(tv[0], ti[0], cn1 - 2.f * acc[nt][1], c0 + 1);
            ins4(tv[1], ti[1], cn0 - 2.f * acc[nt][2], c0);
            ins4(tv[1], ti[1], cn1 - 2.f * acc[nt][3], c0 + 1);
        }
        __syncthreads();
    }

    // final: quad reduce + guarded exact fp64 rescore
    const unsigned qmask = 0xFu << (lane & ~3);
    #pragma unroll
    for (int s = 0; s < 2; s++) {
        int row = row0 + rb + gid + s * 8;
        float m = tv[s][0];
        m = fminf(m, __shfl_xor_sync(qmask, m, 1));
        m = fminf(m, __shfl_xor_sync(qmask, m, 2));
        float thr = m + DELTA;
        int cnt = (tv[s][0] <= thr) + (tv[s][1] <= thr) + (tv[s][2] <= thr) + (tv[s][3] <= thr);
        int tot = cnt;
        tot += __shfl_xor_sync(qmask, tot, 1);
        tot += __shfl_xor_sync(qmask, tot, 2);

        int winner;
        if (tot == 1) {
            int cand = (tv[s][0] <= thr) ? ti[s][0] : 0x7fffffff;
            cand = min(cand, __shfl_xor_sync(qmask, cand, 1));
            cand = min(cand, __shfl_xor_sync(qmask, cand, 2));
            winner = cand;
        } else {
            // fp64 exact rescore of all candidates within thr -> true argmin
            const float* zr = z + (size_t)row * D;
            double zs = 0.0;
            #pragma unroll 8
            for (int j = 0; j < 64; j++) {
                double zv = (double)__ldg(zr + 4 * j + t4);
                zs += zv * zv;
            }
            zs += __shfl_xor_sync(qmask, zs, 1);
            zs += __shfl_xor_sync(qmask, zs, 2);

            double bc = 1.0e300; int bi = 0x7fffffff;
            #pragma unroll
            for (int src = 0; src < 4; src++) {
                #pragma unroll
                for (int j = 0; j < 4; j++) {
                    float v  = __shfl_sync(qmask, tv[s][j], (lane & ~3) + src);
                    int   ci = __shfl_sync(qmask, ti[s][j], (lane & ~3) + src);
                    if (v <= thr) {
                        const float* cr = cb + (size_t)ci * D;
                        double sacc = 0.0;
                        #pragma unroll 8
                        for (int jj = 0; jj < 64; jj++) {
                            double zv = (double)__ldg(zr + 4 * jj + t4);
                            double cv = (double)__ldg(cr + 4 * jj + t4);
                            sacc += zv * cv;
                        }
                        sacc += __shfl_xor_sync(qmask, sacc, 1);
                        sacc += __shfl_xor_sync(qmask, sacc, 2);
                        double cost = zs + g_cnd[ci] - 2.0 * sacc;
                        if (cost < bc || (cost == bc && ci < bi)) { bc = cost; bi = ci; }
                    }
                }
            }
            winner = bi;
        }
        if (t4 == 0) {
            g_idx[row] = winner;
            atomicAdd(&g_counts[winner], 1);
        }
    }
}

// ------------------- kernel 2: gather writeback -------------------
__global__ void vq_write(const float* __restrict__ z, const float* __restrict__ cb,
                         float* __restrict__ out) {
    int i = blockIdx.x * blockDim.x + threadIdx.x;   // float4 index, 4194304 total
    int row = i >> 6;
    int d4  = i & 63;
    int idx = g_idx[row];
    const float4 zv = *(const float4*)(z  + ((size_t)row << 8) + d4 * 4);
    const float4 cv = __ldg((const float4*)(cb + ((size_t)idx << 8) + d4 * 4));
    float4 o;
    o.x = zv.x + (cv.x - zv.x);   // exact STE arithmetic: z + (c - z)
    o.y = zv.y + (cv.y - zv.y);
    o.z = zv.z + (cv.z - zv.z);
    o.w = zv.w + (cv.w - zv.w);
    *(float4*)(out + ((size_t)row << 8) + d4 * 4) = o;
}

// ------------------- kernel 3: loss + perplexity -------------------
__global__ void vq_scalars(float* __restrict__ out, int out_size) {
    __shared__ float red[1024];
    int t = threadIdx.x;
    float e = (float)g_counts[t] * (1.0f / 65536.0f);
    red[t] = e * logf(e + 1e-10f);
    __syncthreads();
    for (int sft = 512; sft > 0; sft >>= 1) {
        if (t < sft) red[t] += red[t + sft];
        __syncthreads();
    }
    if (t == 0) {
        if (out_size >= ND + 1) out[ND] = 0.0f;             // loss (eval)
        if (out_size >= ND + 2) out[ND + 1] = expf(-red[0]); // perplexity
    }
}

// ------------------- launch -------------------
extern "C" void kernel_launch(void* const* d_in, const int* in_sizes, int n_in,
                              void* d_out, int out_size) {
    const float* z  = (const float*)d_in[0];
    const float* cb = (const float*)d_in[1];
    float* out = (float*)d_out;

    cudaFuncSetAttribute(vq_main, cudaFuncAttributeMaxDynamicSharedMemorySize, SMEM_TOT);

    vq_prep<<<4, 256>>>(cb);
    vq_main<<<NROWS / ROWS_BLK, 256, SMEM_TOT>>>(z, cb);
    vq_write<<<(NROWS * (D / 4)) / 256, 256>>>(z, cb, out);
    vq_scalars<<<1, 1024>>>(out, out_size);
}

// round 3
// speedup vs baseline: 1.2469x; 1.2469x over previous
#include <cuda_runtime.h>
#include <cuda_bf16.h>
#include <cstdint>

#define D        256
#define K        1024
#define NROWS    65536
#define ROWS_BLK 128
#define COLS_TILE 128
#define NTILES   (K / COLS_TILE)   // 8
#define KSTEPS   16                 // 256 / 16
#define PADB     544                // smem row stride in bytes (272 bf16)
#define DELTA    1.25f
#define ND       (NROWS * D)        // 16777216

// ---- device scratch (no allocations allowed) ----
__device__ __nv_bfloat16 g_cbp[K * D];   // bf16 codebook, k-permuted
__device__ float  g_cn[K];               // fp32 row norms ||c||^2 (screen)
__device__ double g_cnd[K];              // fp64 row norms ||c||^2 (rescore)
__device__ int    g_counts[K];
__device__ int    g_idx[NROWS];

// permutation within each 16-element k chunk so a quad-lane LDS.64 yields
// one mma fragment register pair {k=2q,2q+1, k=2q+8,2q+9}.
__device__ __host__ __forceinline__ int permpos(int d) {
    int chunk = d >> 4, m = d & 15;
    return (chunk << 4) + (((m & 7) >> 1) << 2) + ((m >> 3) << 1) + (m & 1);
}

// ------------------- kernel 0: prep -------------------
__global__ void vq_prep(const float* __restrict__ cb) {
    int t = blockIdx.x * blockDim.x + threadIdx.x;
    if (t >= K) return;
    const float* row = cb + (size_t)t * D;
    float  nrm  = 0.f;
    double nrmd = 0.0;
    for (int d = 0; d < D; d++) {
        float v = row[d];
        nrm  += v * v;
        nrmd += (double)v * (double)v;
        g_cbp[t * D + permpos(d)] = __float2bfloat16(v);
    }
    g_cn[t]  = nrm;
    g_cnd[t] = nrmd;
    g_counts[t] = 0;
}

// top-4 insertion (strict <, earlier (smaller) indices win ties)
__device__ __forceinline__ void ins4(float (&v)[4], int (&ix)[4], float x, int c) {
    if (x < v[3]) {
        if (x < v[1]) {
            if (x < v[0]) {
                v[3]=v[2]; ix[3]=ix[2]; v[2]=v[1]; ix[2]=ix[1];
                v[1]=v[0]; ix[1]=ix[0]; v[0]=x; ix[0]=c;
            } else {
                v[3]=v[2]; ix[3]=ix[2]; v[2]=v[1]; ix[2]=ix[1];
                v[1]=x; ix[1]=c;
            }
        } else {
            if (x < v[2]) { v[3]=v[2]; ix[3]=ix[2]; v[2]=x; ix[2]=c; }
            else          { v[3]=x; ix[3]=c; }
        }
    }
}

// ------------------- kernel 1: main screen + rescore -------------------
#define SMEM_Z    0
#define SMEM_CB0  (ROWS_BLK * PADB)                 // 69632
#define SMEM_CB1  (SMEM_CB0 + COLS_TILE * PADB)     // 139264
#define SMEM_TOT  (SMEM_CB1 + COLS_TILE * PADB)     // 208896

__global__ __launch_bounds__(256, 1)
void vq_main(const float* __restrict__ z, const float* __restrict__ cb) {
    extern __shared__ char sm[];
    const int tid  = threadIdx.x;
    const int wid  = tid >> 5;
    const int lane = tid & 31;
    const int gid  = lane >> 2;
    const int t4   = lane & 3;
    const int row0 = blockIdx.x * ROWS_BLK;

    // cp.async copy of a 128-col codebook tile (already bf16+permuted in gmem)
    auto copy_tile = [&](int ct, int buf) {
        const char* src = (const char*)g_cbp + (size_t)ct * COLS_TILE * D * 2;
        char* dstb = sm + (buf ? SMEM_CB1 : SMEM_CB0);
        #pragma unroll
        for (int i = 0; i < 16; i++) {
            int idx = i * 256 + tid;           // 4096 chunks of 16B
            int r = idx >> 5, c = idx & 31;
            uint32_t da = (uint32_t)__cvta_generic_to_shared(dstb + r * PADB + c * 16);
            const char* s = src + r * (D * 2) + c * 16;
            asm volatile("cp.async.cg.shared.global [%0], [%1], 16;\n" :: "r"(da), "l"(s));
        }
        asm volatile("cp.async.commit_group;\n");
    };

    copy_tile(0, 0);

    // stage z tile: fp32 -> bf16, permuted layout
    {
        const float* zsrc = z + (size_t)row0 * D;
        #pragma unroll 4
        for (int i = 0; i < 64; i++) {
            int idx = i * 256 + tid;           // 16384 bf16 pairs
            int r = idx >> 7, j = idx & 127;
            int k = 2 * j;
            float2 v = *(const float2*)(zsrc + (size_t)r * D + k);
            __nv_bfloat162 b = __floats2bfloat162_rn(v.x, v.y);
            *(uint32_t*)(sm + SMEM_Z + r * PADB + permpos(k) * 2) = *(uint32_t*)&b;
        }
    }

    // per-lane top-4 for 2 row slots (rows gid and gid+8 of this warp's m-tile)
    float tv[2][4]; int ti[2][4];
    #pragma unroll
    for (int s = 0; s < 2; s++)
        #pragma unroll
        for (int j = 0; j < 4; j++) { tv[s][j] = 3.4e38f; ti[s][j] = 0; }

    const int rb = wid * 16;
    const uint32_t a_base = (uint32_t)(SMEM_Z + (rb + gid) * PADB + t4 * 8);

    for (int tile = 0; tile < NTILES; tile++) {
        asm volatile("cp.async.wait_group 0;\n" ::: "memory");
        __syncthreads();
        if (tile + 1 < NTILES) copy_tile(tile + 1, (tile + 1) & 1);

        const char* cbbuf = sm + ((tile & 1) ? SMEM_CB1 : SMEM_CB0);

        // two sequential 64-col halves -> acc stays at 32 registers
        #pragma unroll 1
        for (int half = 0; half < 2; half++) {
            float acc[8][4];
            #pragma unroll
            for (int nt = 0; nt < 8; nt++)
                acc[nt][0] = acc[nt][1] = acc[nt][2] = acc[nt][3] = 0.f;

            const char* bbase = cbbuf + (half * 64) * PADB + t4 * 8;

            #pragma unroll 4
            for (int ks = 0; ks < KSTEPS; ks++) {
                uint2 alo = *(const uint2*)(sm + a_base + ks * 32);
                uint2 ahi = *(const uint2*)(sm + a_base + 8 * PADB + ks * 32);
                uint32_t a0 = alo.x, a2 = alo.y, a1 = ahi.x, a3 = ahi.y;
                #pragma unroll
                for (int nt = 0; nt < 8; nt++) {
                    uint2 bb = *(const uint2*)(bbase + (nt * 8 + gid) * PADB + ks * 32);
                    asm volatile(
                        "mma.sync.aligned.m16n8k16.row.col.f32.bf16.bf16.f32 "
                        "{%0,%1,%2,%3}, {%4,%5,%6,%7}, {%8,%9}, {%0,%1,%2,%3};\n"
                        : "+f"(acc[nt][0]), "+f"(acc[nt][1]), "+f"(acc[nt][2]), "+f"(acc[nt][3])
                        : "r"(a0), "r"(a1), "r"(a2), "r"(a3), "r"(bb.x), "r"(bb.y));
                }
            }

            // epilogue: cost = ||c||^2 - 2*score, push into top-4
            int colbase = tile * COLS_TILE + half * 64 + 2 * t4;
            #pragma unroll
            for (int nt = 0; nt < 8; nt++) {
                int c0 = colbase + nt * 8;
                float cn0 = __ldg(&g_cn[c0]);
                float cn1 = __ldg(&g_cn[c0 + 1]);
                ins4(tv[0], ti[0], cn0 - 2.f * acc[nt][0], c0);
                ins4(tv[0], ti[0], cn1 - 2.f * acc[nt][1], c0 + 1);
                ins4(tv[1], ti[1], cn0 - 2.f * acc[nt][2], c0);
                ins4(tv[1], ti[1], cn1 - 2.f * acc[nt][3], c0 + 1);
            }
        }
        __syncthreads();
    }

    // final: quad reduce + guarded exact fp64 rescore
    const unsigned qmask = 0xFu << (lane & ~3);
    #pragma unroll 1
    for (int s = 0; s < 2; s++) {
        int row = row0 + rb + gid + s * 8;
        float m = tv[s][0];
        m = fminf(m, __shfl_xor_sync(qmask, m, 1));
        m = fminf(m, __shfl_xor_sync(qmask, m, 2));
        float thr = m + DELTA;
        int cnt = (tv[s][0] <= thr) + (tv[s][1] <= thr) + (tv[s][2] <= thr) + (tv[s][3] <= thr);
        int tot = cnt;
        tot += __shfl_xor_sync(qmask, tot, 1);
        tot += __shfl_xor_sync(qmask, tot, 2);

        int winner;
        if (tot == 1) {
            int cand = (tv[s][0] <= thr) ? ti[s][0] : 0x7fffffff;
            cand = min(cand, __shfl_xor_sync(qmask, cand, 1));
            cand = min(cand, __shfl_xor_sync(qmask, cand, 2));
            winner = cand;
        } else {
            // fp64 exact rescore of all candidates within thr -> true argmin
            const float* zr = z + (size_t)row * D;
            double zs = 0.0;
            #pragma unroll 8
            for (int j = 0; j < 64; j++) {
                double zv = (double)__ldg(zr + 4 * j + t4);
                zs += zv * zv;
            }
            zs += __shfl_xor_sync(qmask, zs, 1);
            zs += __shfl_xor_sync(qmask, zs, 2);

            double bc = 1.0e300; int bi = 0x7fffffff;
            #pragma unroll 1
            for (int src = 0; src < 4; src++) {
                #pragma unroll 1
                for (int j = 0; j < 4; j++) {
                    float v  = __shfl_sync(qmask, tv[s][j], (lane & ~3) + src);
                    int   ci = __shfl_sync(qmask, ti[s][j], (lane & ~3) + src);
                    if (v <= thr) {
                        const float* cr = cb + (size_t)ci * D;
                        double sacc = 0.0;
                        #pragma unroll 8
                        for (int jj = 0; jj < 64; jj++) {
                            double zv = (double)__ldg(zr + 4 * jj + t4);
                            double cv = (double)__ldg(cr + 4 * jj + t4);
                            sacc += zv * cv;
                        }
                        sacc += __shfl_xor_sync(qmask, sacc, 1);
                        sacc += __shfl_xor_sync(qmask, sacc, 2);
                        double cost = zs + g_cnd[ci] - 2.0 * sacc;
                        if (cost < bc || (cost == bc && ci < bi)) { bc = cost; bi = ci; }
                    }
                }
            }
            winner = bi;
        }
        if (t4 == 0) {
            g_idx[row] = winner;
            atomicAdd(&g_counts[winner], 1);
        }
    }
}

// ------------------- kernel 2: gather writeback -------------------
__global__ void vq_write(const float* __restrict__ z, const float* __restrict__ cb,
                         float* __restrict__ out) {
    int i = blockIdx.x * blockDim.x + threadIdx.x;   // float4 index, 4194304 total
    int row = i >> 6;
    int d4  = i & 63;
    int idx = g_idx[row];
    const float4 zv = *(const float4*)(z  + ((size_t)row << 8) + d4 * 4);
    const float4 cv = __ldg((const float4*)(cb + ((size_t)idx << 8) + d4 * 4));
    float4 o;
    o.x = zv.x + (cv.x - zv.x);   // exact STE arithmetic: z + (c - z)
    o.y = zv.y + (cv.y - zv.y);
    o.z = zv.z + (cv.z - zv.z);
    o.w = zv.w + (cv.w - zv.w);
    *(float4*)(out + ((size_t)row << 8) + d4 * 4) = o;
}

// ------------------- kernel 3: loss + perplexity -------------------
__global__ void vq_scalars(float* __restrict__ out, int out_size) {
    __shared__ float red[1024];
    int t = threadIdx.x;
    float e = (float)g_counts[t] * (1.0f / 65536.0f);
    red[t] = e * logf(e + 1e-10f);
    __syncthreads();
    for (int sft = 512; sft > 0; sft >>= 1) {
        if (t < sft) red[t] += red[t + sft];
        __syncthreads();
    }
    if (t == 0) {
        if (out_size >= ND + 1) out[ND] = 0.0f;             // loss (eval)
        if (out_size >= ND + 2) out[ND + 1] = expf(-red[0]); // perplexity
    }
}

// ------------------- launch -------------------
extern "C" void kernel_launch(void* const* d_in, const int* in_sizes, int n_in,
                              void* d_out, int out_size) {
    const float* z  = (const float*)d_in[0];
    const float* cb = (const float*)d_in[1];
    float* out = (float*)d_out;

    cudaFuncSetAttribute(vq_main, cudaFuncAttributeMaxDynamicSharedMemorySize, SMEM_TOT);

    vq_prep<<<4, 256>>>(cb);
    vq_main<<<NROWS / ROWS_BLK, 256, SMEM_TOT>>>(z, cb);
    vq_write<<<(NROWS * (D / 4)) / 256, 256>>>(z, cb, out);
    vq_scalars<<<1, 1024>>>(out, out_size);
}